// round 17
// baseline (speedup 1.0000x reference)
#include <cuda_runtime.h>
#include <cuda_bf16.h>
#include <mma.h>
#include <math.h>
#include <stdint.h>

using namespace nvcuda;

#define N_NODES 16000
#define N_EDGES 256000
#define D 128
#define H 4
#define G3 (3*D)        // 384
#define HD (H*D)        // 512
#define ALPHA 0.2f

// ---------------- static scratch ----------------
__device__ float g_Wh[N_NODES * H * D];
__device__ float g_ssrc[N_NODES * H];
__device__ float g_sdst[N_NODES * H];
__device__ float g_hprime[N_NODES * H * D];   // x reshaped (N, 512)
__device__ float g_gi[N_NODES * G3];
__device__ float g_gh[N_NODES * G3];
__device__ float g_WT[H * D * D];             // W transposed: [h][e][d]
__device__ __align__(16) int g_deg[N_NODES];
__device__ int   g_fill[N_NODES];
__device__ __align__(16) int g_rowptr[N_NODES + 4];
__device__ int   g_esrc[N_EDGES];             // src node id per CSR slot

// pre-split bf16 operands (hi/lo)
__device__ __align__(16) __nv_bfloat16 g_h_hi[N_NODES * D];
__device__ __align__(16) __nv_bfloat16 g_h_lo[N_NODES * D];
__device__ __align__(16) __nv_bfloat16 g_hp_hi[N_NODES * HD];
__device__ __align__(16) __nv_bfloat16 g_hp_lo[N_NODES * HD];
__device__ __align__(16) __nv_bfloat16 g_wt_hi[H * D * D];
__device__ __align__(16) __nv_bfloat16 g_wt_lo[H * D * D];
__device__ __align__(16) __nv_bfloat16 g_wih_hi[G3 * HD];
__device__ __align__(16) __nv_bfloat16 g_wih_lo[G3 * HD];
__device__ __align__(16) __nv_bfloat16 g_whh_hi[G3 * D];
__device__ __align__(16) __nv_bfloat16 g_whh_lo[G3 * D];

// ---------------- helpers ----------------
__device__ __forceinline__ uint32_t smem_u32(const void* p) {
    uint32_t a;
    asm("{ .reg .u64 t; cvta.to.shared.u64 t, %1; cvt.u32.u64 %0, t; }" : "=r"(a) : "l"(p));
    return a;
}
__device__ __forceinline__ void cp16(uint32_t dst, const void* src) {
    asm volatile("cp.async.cg.shared.global [%0], [%1], 16;" :: "r"(dst), "l"(src));
}
#define CP_COMMIT() asm volatile("cp.async.commit_group;" ::: "memory")
#define CP_WAIT0()  asm volatile("cp.async.wait_group 0;" ::: "memory")
#define CP_WAIT1()  asm volatile("cp.async.wait_group 1;" ::: "memory")

__device__ __forceinline__ void split1(float x, __nv_bfloat16& hi, __nv_bfloat16& lo) {
    hi = __float2bfloat16_rn(x);
    lo = __float2bfloat16_rn(x - __bfloat162float(hi));
}
// split 4 floats -> 2x bf16x2 hi + 2x bf16x2 lo (vectorized stores)
__device__ __forceinline__ void split4_store(float4 v, __nv_bfloat16* hi, __nv_bfloat16* lo, size_t i4) {
    __nv_bfloat162 h0, h1, l0, l1;
    split1(v.x, h0.x, l0.x); split1(v.y, h0.y, l0.y);
    split1(v.z, h1.x, l1.x); split1(v.w, h1.y, l1.y);
    ((__nv_bfloat162*)hi)[i4 * 2 + 0] = h0;
    ((__nv_bfloat162*)hi)[i4 * 2 + 1] = h1;
    ((__nv_bfloat162*)lo)[i4 * 2 + 0] = l0;
    ((__nv_bfloat162*)lo)[i4 * 2 + 1] = l1;
}

// ---------------- pure-bf16 cp.async double-buffered wmma GEMM ----------------
// C[128 x 128-tile] = A[M,K] @ B[NB,K]^T, 3-term: AhBh + AhBl + AlBh (fp32 accum)
// smem: 2 stages x 4 tiles [128][40] bf16 (10240 B each) = 81920 B
#define TILE_B 10240
#define STAGE_B (4 * TILE_B)
#define SMEM_GEMM (2 * STAGE_B)
template<int KTOT>
__device__ __forceinline__ void tc_gemm_bf(const __nv_bfloat16* __restrict__ Ahi,
                                           const __nv_bfloat16* __restrict__ Alo,
                                           const __nv_bfloat16* __restrict__ Bhi,
                                           const __nv_bfloat16* __restrict__ Blo,
                                           float* __restrict__ C, int ldC) {
    extern __shared__ char sm[];
    uint32_t sm_u = smem_u32(sm);

    int tid = threadIdx.x;
    int wid = tid >> 5;
    int warpM = wid >> 1;          // 0..3
    int warpN = wid & 1;           // 0..1
    int row0 = blockIdx.x * 128;

    const __nv_bfloat16* srcs[4] = { Ahi + (size_t)row0 * KTOT, Alo + (size_t)row0 * KTOT, Bhi, Blo };

    wmma::fragment<wmma::accumulator, 16, 16, 16, float> acc[2][4];
    #pragma unroll
    for (int i = 0; i < 2; i++)
        #pragma unroll
        for (int j = 0; j < 4; j++)
            wmma::fill_fragment(acc[i][j], 0.0f);

    const int KC = KTOT / 32;

    // issue one chunk into a stage: 4 tiles x 512 16B-segments = 8 cp16/thread
    auto issue = [&](int c, int stg) {
        uint32_t base = sm_u + stg * STAGE_B;
        #pragma unroll
        for (int arr = 0; arr < 4; arr++) {
            #pragma unroll
            for (int j = 0; j < 2; j++) {
                int idx = tid + j * 256;         // 0..511
                int r = idx >> 2, seg = idx & 3; // 4 x 16B per 64B row
                cp16(base + arr * TILE_B + r * 80 + seg * 16,
                     srcs[arr] + (size_t)r * KTOT + c * 32 + seg * 8);
            }
        }
        CP_COMMIT();
    };

    issue(0, 0);
    #pragma unroll 1
    for (int c = 0; c < KC; c++) {
        int stg = c & 1;
        if (c + 1 < KC) { issue(c + 1, stg ^ 1); CP_WAIT1(); }
        else            { CP_WAIT0(); }
        __syncthreads();    // chunk c tiles visible to all

        const __nv_bfloat16* Ah = (const __nv_bfloat16*)(sm + stg * STAGE_B + 0 * TILE_B);
        const __nv_bfloat16* Al = (const __nv_bfloat16*)(sm + stg * STAGE_B + 1 * TILE_B);
        const __nv_bfloat16* Bh = (const __nv_bfloat16*)(sm + stg * STAGE_B + 2 * TILE_B);
        const __nv_bfloat16* Bl = (const __nv_bfloat16*)(sm + stg * STAGE_B + 3 * TILE_B);

        #pragma unroll
        for (int ks = 0; ks < 2; ks++) {
            wmma::fragment<wmma::matrix_a, 16, 16, 16, __nv_bfloat16, wmma::row_major> a_hi[2], a_lo[2];
            #pragma unroll
            for (int fm = 0; fm < 2; fm++) {
                wmma::load_matrix_sync(a_hi[fm], &Ah[(warpM * 32 + fm * 16) * 40 + ks * 16], 40);
                wmma::load_matrix_sync(a_lo[fm], &Al[(warpM * 32 + fm * 16) * 40 + ks * 16], 40);
            }
            #pragma unroll
            for (int fn = 0; fn < 4; fn++) {
                wmma::fragment<wmma::matrix_b, 16, 16, 16, __nv_bfloat16, wmma::col_major> b_hi, b_lo;
                wmma::load_matrix_sync(b_hi, &Bh[(warpN * 64 + fn * 16) * 40 + ks * 16], 40);
                wmma::load_matrix_sync(b_lo, &Bl[(warpN * 64 + fn * 16) * 40 + ks * 16], 40);
                #pragma unroll
                for (int fm = 0; fm < 2; fm++) {
                    wmma::mma_sync(acc[fm][fn], a_hi[fm], b_hi, acc[fm][fn]);
                    wmma::mma_sync(acc[fm][fn], a_hi[fm], b_lo, acc[fm][fn]);
                    wmma::mma_sync(acc[fm][fn], a_lo[fm], b_hi, acc[fm][fn]);
                }
            }
        }
        __syncthreads();    // reads done before this stage is refilled
    }

    #pragma unroll
    for (int fm = 0; fm < 2; fm++) {
        int row = row0 + warpM * 32 + fm * 16;
        #pragma unroll
        for (int fn = 0; fn < 4; fn++) {
            int col = warpN * 64 + fn * 16;
            wmma::store_matrix_sync(&C[(size_t)row * ldC + col], acc[fm][fn], ldC, wmma::mem_row_major);
        }
    }
}

__global__ void __launch_bounds__(256) k_wh_tc() {
    int head = blockIdx.y;
    tc_gemm_bf<128>(g_h_hi, g_h_lo, g_wt_hi + (head << 14), g_wt_lo + (head << 14),
                    g_Wh + (head << 7), HD);
}
__global__ void __launch_bounds__(256) k_gi_tc() {
    int col0 = blockIdx.y * 128;
    tc_gemm_bf<HD>(g_hp_hi, g_hp_lo, g_wih_hi + (size_t)col0 * HD, g_wih_lo + (size_t)col0 * HD,
                   g_gi + col0, G3);
}
__global__ void __launch_bounds__(256) k_gh_tc() {
    int col0 = blockIdx.y * 128;
    tc_gemm_bf<D>(g_h_hi, g_h_lo, g_whh_hi + (size_t)col0 * D, g_whh_lo + (size_t)col0 * D,
                  g_gh + col0, G3);
}

// ---------------- split kernels (device globals resolved in device code) ----------------
__global__ void k_split_h(const float* __restrict__ hin) {    // h: 2,048,000 floats
    int i = blockIdx.x * blockDim.x + threadIdx.x;
    if (i < N_NODES * D / 4)
        split4_store(((const float4*)hin)[i], g_h_hi, g_h_lo, i);
}
__global__ void k_split_hprime() {                            // hprime: 8,192,000 floats
    int i = blockIdx.x * blockDim.x + threadIdx.x;
    if (i < N_NODES * HD / 4)
        split4_store(((const float4*)g_hprime)[i], g_hp_hi, g_hp_lo, i);
}
__global__ void k_split_wts(const float* __restrict__ Wih, const float* __restrict__ Whh) {
    int i = blockIdx.x * blockDim.x + threadIdx.x;
    const int N1 = H * D * D / 4;          // 16384 (from g_WT)
    const int N2 = G3 * HD / 4;            // 49152
    const int N3 = G3 * D / 4;             // 12288
    if (i < N1) {
        split4_store(((const float4*)g_WT)[i], g_wt_hi, g_wt_lo, i);
    } else if (i < N1 + N2) {
        int j = i - N1;
        split4_store(((const float4*)Wih)[j], g_wih_hi, g_wih_lo, j);
    } else if (i < N1 + N2 + N3) {
        int j = i - N1 - N2;
        split4_store(((const float4*)Whh)[j], g_whh_hi, g_whh_lo, j);
    }
}

// ---------------- init: zero counters + transpose W (one launch) ----------------
__global__ void k_init(const float* __restrict__ W) {
    int i = blockIdx.x * blockDim.x + threadIdx.x;
    if (i < N_NODES) { g_deg[i] = 0; g_fill[i] = 0; }
    if (i < H * D * D) {
        int h = i >> 14, rem = i & 16383, d = rem >> 7, e = rem & 127;
        g_WT[(h << 14) + (e << 7) + d] = W[i];
    }
}

__global__ void k_count(const int* __restrict__ dst) {
    int e = blockIdx.x * blockDim.x + threadIdx.x;
    if (e < N_EDGES) atomicAdd(&g_deg[dst[e]], 1);
}

// fast single-block scan: 1000 active thr x 16 elems (int4), warp-shuffle based
__global__ void __launch_bounds__(1024) k_scan() {
    __shared__ int wsum[32];
    int t = threadIdx.x;
    int lane = t & 31, warp = t >> 5;
    bool active = t < 1000;
    int v[16];
    int s = 0;
    if (active) {
        const int4* d4 = (const int4*)g_deg;
        #pragma unroll
        for (int i = 0; i < 4; i++) {
            int4 x = d4[t * 4 + i];
            v[i * 4 + 0] = s; s += x.x;
            v[i * 4 + 1] = s; s += x.y;
            v[i * 4 + 2] = s; s += x.z;
            v[i * 4 + 3] = s; s += x.w;
        }
    }
    int incl = s;
    #pragma unroll
    for (int o = 1; o < 32; o <<= 1) {
        int y = __shfl_up_sync(0xffffffffu, incl, o);
        if (lane >= o) incl += y;
    }
    if (lane == 31) wsum[warp] = incl;
    __syncthreads();
    if (warp == 0) {
        int w = wsum[lane];
        #pragma unroll
        for (int o = 1; o < 32; o <<= 1) {
            int y = __shfl_up_sync(0xffffffffu, w, o);
            if (lane >= o) w += y;
        }
        wsum[lane] = w;
    }
    __syncthreads();
    int warpoff = (warp > 0) ? wsum[warp - 1] : 0;
    int throff = warpoff + (incl - s);
    if (active) {
        int4* r4 = (int4*)g_rowptr;
        #pragma unroll
        for (int i = 0; i < 4; i++)
            r4[t * 4 + i] = make_int4(throff + v[i * 4 + 0], throff + v[i * 4 + 1],
                                      throff + v[i * 4 + 2], throff + v[i * 4 + 3]);
    }
    if (t == 1023) g_rowptr[N_NODES] = wsum[31];
}

__global__ void k_fill(const int* __restrict__ src, const int* __restrict__ dst) {
    int e = blockIdx.x * blockDim.x + threadIdx.x;
    if (e < N_EDGES) {
        int d = dst[e];
        int pos = g_rowptr[d] + atomicAdd(&g_fill[d], 1);
        g_esrc[pos] = src[e];
    }
}

// ---------------- scores ----------------
__global__ void __launch_bounds__(256) k_scores(const float* __restrict__ a) {
    int tid = threadIdx.x, lane = tid & 31, warp = tid >> 5;
    int w = blockIdx.x * 8 + warp;
    int head = w & (H - 1);
    float4 wv = ((const float4*)(g_Wh + w * D))[lane];
    float4 a1 = *(const float4*)&a[head * (2 * D) + lane * 4];
    float4 a2 = *(const float4*)&a[head * (2 * D) + D + lane * 4];
    float d1 = wv.x * a1.x + wv.y * a1.y + wv.z * a1.z + wv.w * a1.w;
    float d2 = wv.x * a2.x + wv.y * a2.y + wv.z * a2.z + wv.w * a2.w;
    #pragma unroll
    for (int o = 16; o; o >>= 1) {
        d1 += __shfl_xor_sync(0xffffffffu, d1, o);
        d2 += __shfl_xor_sync(0xffffffffu, d2, o);
    }
    if (lane == 0) { g_ssrc[w] = d1; g_sdst[w] = d2; }
}

// ---------------- single-pass online-softmax aggregate ----------------
__global__ void __launch_bounds__(128) k_agg() {
    int n = blockIdx.x;
    int head = threadIdx.x >> 5;
    int lane = threadIdx.x & 31;
    int start = g_rowptr[n], end = g_rowptr[n + 1];
    float4 acc = make_float4(0.f, 0.f, 0.f, 0.f);
    if (end > start) {
        float sd = g_sdst[n * H + head];
        float m = -1e30f, sum = 0.f;
        for (int jb = start; jb < end; jb += 32) {
            int myidx = jb + lane;
            int s_pre = 0;
            float v_pre = 0.f;
            if (myidx < end) {
                s_pre = g_esrc[myidx];
                v_pre = g_ssrc[s_pre * H + head];
            }
            int cnt = min(32, end - jb);
            for (int t = 0; t < cnt; t++) {
                int s = __shfl_sync(0xffffffffu, s_pre, t);
                float v = __shfl_sync(0xffffffffu, v_pre, t) + sd;
                v = v >= 0.f ? v : ALPHA * v;
                float scale = 1.f;
                if (v > m) { scale = __expf(m - v); m = v; }
                float att = __expf(v - m);
                float4 wv = ((const float4*)(g_Wh + (s * H + head) * D))[lane];
                sum = sum * scale + att;
                acc.x = fmaf(att, wv.x, acc.x * scale);
                acc.y = fmaf(att, wv.y, acc.y * scale);
                acc.z = fmaf(att, wv.z, acc.z * scale);
                acc.w = fmaf(att, wv.w, acc.w * scale);
            }
        }
        float inv = 1.0f / sum;
        acc.x *= inv; acc.y *= inv; acc.z *= inv; acc.w *= inv;
    }
    ((float4*)(g_hprime + (n * H + head) * D))[lane] = acc;
}

// ---------------- GRU elementwise (bias folded here) ----------------
__global__ void __launch_bounds__(256) k_gru(const float* __restrict__ hin,
                                             const float* __restrict__ bih,
                                             const float* __restrict__ bhh,
                                             float* __restrict__ out) {
    int idx = blockIdx.x * blockDim.x + threadIdx.x;
    if (idx >= N_NODES * D) return;
    int n = idx >> 7;
    int d = idx & (D - 1);
    float ir = g_gi[n * G3 + d]          + bih[d];
    float iz = g_gi[n * G3 + D + d]      + bih[D + d];
    float in_ = g_gi[n * G3 + 2 * D + d] + bih[2 * D + d];
    float hr = g_gh[n * G3 + d]          + bhh[d];
    float hz = g_gh[n * G3 + D + d]      + bhh[D + d];
    float hn = g_gh[n * G3 + 2 * D + d]  + bhh[2 * D + d];
    float r = 1.0f / (1.0f + __expf(-(ir + hr)));
    float z = 1.0f / (1.0f + __expf(-(iz + hz)));
    float nv = tanhf(in_ + r * hn);
    out[idx] = (1.0f - z) * nv + z * hin[idx];
}

// ---------------- launch ----------------
extern "C" void kernel_launch(void* const* d_in, const int* in_sizes, int n_in,
                              void* d_out, int out_size) {
    const float* h_ptr = (const float*)d_in[0];
    const float* W     = (const float*)d_in[1];
    const float* a     = (const float*)d_in[2];
    const float* W_ih  = (const float*)d_in[3];
    const float* W_hh  = (const float*)d_in[4];
    const float* b_ih  = (const float*)d_in[5];
    const float* b_hh  = (const float*)d_in[6];
    const int*   src   = (const int*)d_in[7];
    const int*   dst   = (const int*)d_in[8];
    float* out = (float*)d_out;
    (void)in_sizes; (void)n_in; (void)out_size;

    cudaFuncSetAttribute(k_wh_tc, cudaFuncAttributeMaxDynamicSharedMemorySize, SMEM_GEMM);
    cudaFuncSetAttribute(k_gi_tc, cudaFuncAttributeMaxDynamicSharedMemorySize, SMEM_GEMM);
    cudaFuncSetAttribute(k_gh_tc, cudaFuncAttributeMaxDynamicSharedMemorySize, SMEM_GEMM);

    // init (zero counters + W transpose), CSR build, operand splits
    k_init<<<(H * D * D + 255) / 256, 256>>>(W);
    k_count<<<(N_EDGES + 255) / 256, 256>>>(dst);
    k_split_h<<<(N_NODES * D / 4 + 255) / 256, 256>>>(h_ptr);
    k_split_wts<<<((H * D * D + G3 * HD + G3 * D) / 4 + 255) / 256, 256>>>(W_ih, W_hh);
    k_scan<<<1, 1024>>>();
    k_fill<<<(N_EDGES + 255) / 256, 256>>>(src, dst);

    // Wh = h @ W[h]
    dim3 g1(N_NODES / 128, H);
    k_wh_tc<<<g1, 256, SMEM_GEMM>>>();

    // attention scores
    k_scores<<<(N_NODES * H) / 8, 256>>>(a);

    // single-pass softmax-aggregate into h'
    k_agg<<<N_NODES, 128>>>();

    // split h' for the gi GEMM
    k_split_hprime<<<(N_NODES * HD / 4 + 255) / 256, 256>>>();

    // gi = x @ W_ih^T
    dim3 g2(N_NODES / 128, 3);
    k_gi_tc<<<g2, 256, SMEM_GEMM>>>();

    // gh = h @ W_hh^T
    k_gh_tc<<<g2, 256, SMEM_GEMM>>>();

    // GRU combine (+ biases)
    k_gru<<<(N_NODES * D + 255) / 256, 256>>>(h_ptr, b_ih, b_hh, out);
}